// round 8
// baseline (speedup 1.0000x reference)
#include <cuda_runtime.h>

#define NCLS 20
#define NSUP 100
#define NQRY 300
#define DDIM 640
#define NTASK 256
#define THREADS 256
#define ROW16 (DDIM / 4)      // 160 16-byte elements per row
#define NCHUNK (DDIM / 32)    // 20 chunks: 8 lanes x 4 floats
#define NGRP (NQRY / 4)       // 75 groups: 4 queries per warp-group (1 per subgroup)
#define PF 5                  // query prefetch ring depth (NCHUNK % PF == 0)

__device__ float g_task_loss[NTASK];

__device__ __forceinline__ unsigned long long ffma2(unsigned long long a,
                                                    unsigned long long b,
                                                    unsigned long long c) {
    unsigned long long d;
    asm("fma.rn.f32x2 %0, %1, %2, %3;" : "=l"(d) : "l"(a), "l"(b), "l"(c));
    return d;
}
__device__ __forceinline__ unsigned long long fadd2(unsigned long long a,
                                                    unsigned long long b) {
    unsigned long long d;
    asm("add.rn.f32x2 %0, %1, %2;" : "=l"(d) : "l"(a), "l"(b));
    return d;
}
__device__ __forceinline__ float2 unpk2(unsigned long long v) {
    float lo, hi;
    asm("mov.b64 {%0, %1}, %2;" : "=f"(lo), "=f"(hi) : "l"(v));
    return make_float2(lo, hi);
}

extern __shared__ float smem_raw[];

__global__ __launch_bounds__(THREADS, 2)
void proto_loss_kernel(const float* __restrict__ sup,
                       const float* __restrict__ qry,
                       const int* __restrict__ tsup,
                       const int* __restrict__ tqry) {
    float* proto  = smem_raw;                    // [20][640]
    float* psq    = proto + NCLS * DDIM;         // [20]
    float* wsum   = psq + NCLS;                  // [8]
    int*   counts = (int*)(wsum + 8);            // [20]
    int*   labels = counts + NCLS;               // [100]
    int*   tqs    = labels + NSUP;               // [300]

    const int b    = blockIdx.x;
    const int tid  = threadIdx.x;
    const int lane = tid & 31;
    const int wid  = tid >> 5;
    const int sub  = (lane >> 3);   // subgroup 0..3
    const int sl   = lane & 7;      // lane within subgroup

    // ======== Phase 1: prototypes ========
    for (int i = tid; i < NCLS * DDIM; i += THREADS) proto[i] = 0.f;
    if (tid < NCLS) counts[tid] = 0;
    if (tid < NSUP) labels[tid] = tsup[b * NSUP + tid];
    for (int i = tid; i < NQRY; i += THREADS) tqs[i] = tqry[b * NQRY + i];
    __syncthreads();
    if (tid < NSUP) atomicAdd(&counts[labels[tid]], 1);

    const float* supb = sup + (size_t)b * NSUP * DDIM;
    for (int d = tid; d < DDIM; d += THREADS) {
        int cur = labels[0];
        float run = 0.f;
        #pragma unroll 5
        for (int s = 0; s < NSUP; s++) {
            int L = labels[s];
            if (L != cur) { proto[cur * DDIM + d] += run; run = 0.f; cur = L; }
            run += supb[s * DDIM + d];
        }
        proto[cur * DDIM + d] += run;
    }
    __syncthreads();

    #pragma unroll
    for (int c = 0; c < NCLS; c++) {
        float inv = 1.f / (float)counts[c];
        for (int d = tid; d < DDIM; d += THREADS) proto[c * DDIM + d] *= inv;
    }
    __syncthreads();

    for (int c = wid; c < NCLS; c += 8) {
        float v = 0.f;
        for (int d = lane; d < DDIM; d += 32) {
            float p = proto[c * DDIM + d];
            v = fmaf(p, p, v);
        }
        #pragma unroll
        for (int o = 16; o; o >>= 1) v += __shfl_xor_sync(0xffffffffu, v, o);
        if (!lane) psq[c] = v;
    }
    __syncthreads();

    // ======== Phase 2: query distances + log-softmax ========
    const ulonglong2* q2 = (const ulonglong2*)(qry + (size_t)b * NQRY * DDIM);
    const ulonglong2* p2base = (const ulonglong2*)proto;
    float nll = 0.f;

    for (int g = wid; g < NGRP; g += 8) {
        const int q = g * 4 + sub;   // this subgroup's query (always < 300)
        const ulonglong2* qrow = q2 + (size_t)q * ROW16 + sl;
        const ulonglong2* prow = p2base + sl;

        unsigned long long acc[NCLS];
        #pragma unroll
        for (int c = 0; c < NCLS; c++) acc[c] = 0ull;

        // ---- prefetch ring: keep PF query LDG.128 in flight per warp ----
        ulonglong2 buf[PF];
        #pragma unroll
        for (int i = 0; i < PF; i++) buf[i] = qrow[i * 8];

        #pragma unroll 5
        for (int ch = 0; ch < NCHUNK; ch++) {
            ulonglong2 va = buf[ch % PF];
            if (ch + PF < NCHUNK) buf[ch % PF] = qrow[(ch + PF) * 8];
            #pragma unroll
            for (int c = 0; c < NCLS; c++) {
                ulonglong2 pv = prow[c * ROW16 + ch * 8];   // broadcast across subgroups
                acc[c] = ffma2(va.x, pv.x, acc[c]);
                acc[c] = ffma2(va.y, pv.y, acc[c]);
            }
        }

        // 3-round butterfly within the 8-lane subgroup
        #pragma unroll
        for (int c = 0; c < NCLS; c++) {
            #pragma unroll
            for (int o = 4; o; o >>= 1)
                acc[c] = fadd2(acc[c], __shfl_xor_sync(0xffffffffu, acc[c], o));
        }

        // epilogue: 1 query per subgroup (redundant across its 8 lanes)
        {
            const int tgt = tqs[q];
            float sv[NCLS];
            float m = -1e30f, st = 0.f;
            #pragma unroll
            for (int c = 0; c < NCLS; c++) {
                float2 x = unpk2(acc[c]);
                float cr = x.x + x.y;
                sv[c] = fmaf(2.f, cr, -psq[c]);   // -dist + const(q) shift
                m = fmaxf(m, sv[c]);
                if (c == tgt) st = sv[c];
            }
            float sum = 0.f;
            #pragma unroll
            for (int c = 0; c < NCLS; c++) sum += __expf(sv[c] - m);
            nll += (m + __logf(sum)) - st;
        }
    }

    // all 8 lanes of a subgroup hold identical nll; full-warp sum / 8 is exact
    #pragma unroll
    for (int o = 16; o; o >>= 1) nll += __shfl_xor_sync(0xffffffffu, nll, o);
    nll *= 0.125f;

    if (!lane) wsum[wid] = nll;
    __syncthreads();
    if (tid == 0) {
        float t = 0.f;
        #pragma unroll
        for (int w = 0; w < 8; w++) t += wsum[w];
        g_task_loss[b] = t * (1.f / (float)NQRY);
    }
}

__global__ void final_reduce_kernel(float* __restrict__ out) {
    __shared__ float s[NTASK];
    int tid = threadIdx.x;
    s[tid] = g_task_loss[tid];
    __syncthreads();
    #pragma unroll
    for (int off = 128; off; off >>= 1) {
        if (tid < off) s[tid] += s[tid + off];
        __syncthreads();
    }
    if (tid == 0) out[0] = s[0] * (1.f / (float)NTASK);
}

// Padding kernel: makes each kernel_launch emit 4 launches so ncu's
// "-s 5 -c 1" (launch index 5 == 1 mod 4) always profiles the MAIN kernel.
__global__ void ncu_align_kernel() {}

extern "C" void kernel_launch(void* const* d_in, const int* in_sizes, int n_in,
                              void* d_out, int out_size) {
    const float* sup = (const float*)d_in[0];
    const float* qry = (const float*)d_in[1];
    const int*   ts  = (const int*)d_in[2];
    const int*   tq  = (const int*)d_in[3];
    float* out = (float*)d_out;

    const size_t SMEM = (size_t)(NCLS * DDIM + NCLS + 8) * sizeof(float)
                      + (size_t)(NCLS + NSUP + NQRY) * sizeof(int);
    cudaFuncSetAttribute(proto_loss_kernel,
                         cudaFuncAttributeMaxDynamicSharedMemorySize, (int)SMEM);
    ncu_align_kernel<<<1, 32>>>();                             // launch 0 (mod 4)
    proto_loss_kernel<<<NTASK, THREADS, SMEM>>>(sup, qry, ts, tq);  // launch 1 (mod 4)
    final_reduce_kernel<<<1, NTASK>>>(out);                    // launch 2 (mod 4)
    ncu_align_kernel<<<1, 32>>>();                             // launch 3 (mod 4)
}